// round 2
// baseline (speedup 1.0000x reference)
#include <cuda_runtime.h>
#include <math.h>

#define HID 128
#define ZDIM 100
#define GCN 32
#define GD 96
#define BATCH 8
#define NPTS 65536
#define NLAYERS 8
#define MAPH 256
#define FDIM ((NLAYERS + 1) * HID)   // 1152

#define XS 132                        // smem row stride in floats (128 + 4 pad)
#define SMEM_FLOATS (2 * 131 * XS + 544)
#define SMEM_BYTES (SMEM_FLOATS * 4)

__device__ float g_freqs[BATCH][FDIM];
__device__ float g_phases[BATCH][FDIM];

// Accurate-enough sin for large args: reduce to [-pi,pi] (Cody-Waite), then MUFU.
__device__ __forceinline__ float fast_sin(float x)
{
    float n = rintf(x * 0.15915494309189535f);      // x / (2*pi)
    float r = fmaf(n, -6.28125f, x);                // 2*pi hi (exact in fp32)
    r = fmaf(n, -1.9353071795864769e-3f, r);        // 2*pi lo
    return __sinf(r);
}

// ---------------------------------------------------------------------------
// Mapping network: z (8x100) -> 3x leaky(256) -> fo (2304) -> freqs/phases
// ---------------------------------------------------------------------------
__global__ void map_kernel(const float* __restrict__ z,
                           const float* __restrict__ w0, const float* __restrict__ b0,
                           const float* __restrict__ w1, const float* __restrict__ b1,
                           const float* __restrict__ w2, const float* __restrict__ b2,
                           const float* __restrict__ w3, const float* __restrict__ b3)
{
    __shared__ float zs[ZDIM];
    __shared__ float ha[MAPH];
    __shared__ float hb[MAPH];
    const int b = blockIdx.x;
    const int tid = threadIdx.x;

    if (tid < ZDIM) zs[tid] = z[b * ZDIM + tid];
    __syncthreads();

    {
        float acc = b0[tid];
        const float* wr = w0 + tid * ZDIM;
        #pragma unroll 4
        for (int k = 0; k < ZDIM; k++) acc = fmaf(wr[k], zs[k], acc);
        ha[tid] = acc > 0.f ? acc : 0.2f * acc;
    }
    __syncthreads();
    {
        float acc = b1[tid];
        const float* wr = w1 + tid * MAPH;
        #pragma unroll 4
        for (int k = 0; k < MAPH; k++) acc = fmaf(wr[k], ha[k], acc);
        hb[tid] = acc > 0.f ? acc : 0.2f * acc;
    }
    __syncthreads();
    {
        float acc = b2[tid];
        const float* wr = w2 + tid * MAPH;
        #pragma unroll 4
        for (int k = 0; k < MAPH; k++) acc = fmaf(wr[k], hb[k], acc);
        ha[tid] = acc > 0.f ? acc : 0.2f * acc;
    }
    __syncthreads();
    for (int o = tid; o < 2 * FDIM; o += MAPH) {
        float acc = b3[o];
        const float* wr = w3 + o * MAPH;
        #pragma unroll 4
        for (int k = 0; k < MAPH; k++) acc = fmaf(wr[k], ha[k], acc);
        if (o < FDIM) g_freqs[b][o] = fmaf(acc, 15.f, 30.f);
        else          g_phases[b][o - FDIM] = acc;
    }
}

// ---------------------------------------------------------------------------
// Main fused kernel helpers
// ---------------------------------------------------------------------------
template <int K>
__device__ __forceinline__ void load_w(float* __restrict__ Wt,
                                       const float* __restrict__ w, int tid)
{
    // global w is [128][K] row-major; store transposed Wt[k][j]
    for (int idx = tid; idx < HID * K; idx += 256) {
        int j = idx / K;
        int k = idx - j * K;
        Wt[k * XS + j] = __ldg(w + idx);
    }
    __syncthreads();
}

__device__ __forceinline__ void load_w_color(float* __restrict__ Wt,
                                             const float* __restrict__ w, int tid)
{
    // color_w is [128][131]; cols 0..2 multiply ray dirs, 3..130 multiply x.
    // Our Xt has x at rows 0..127 and rd at rows 128..130 -> remap.
    for (int idx = tid; idx < HID * 131; idx += 256) {
        int j = idx / 131;
        int k = idx - j * 131;
        int kk = (k < HID) ? (k + 3) : (k - HID);
        Wt[k * XS + j] = __ldg(w + j * 131 + kk);
    }
    __syncthreads();
}

template <int K>
__device__ __forceinline__ void do_film(float* __restrict__ Xt,
                                        const float* __restrict__ Wt,
                                        const float* __restrict__ freq,
                                        const float* __restrict__ phase,
                                        const float* __restrict__ bias,
                                        int tx, int ty)
{
    float fj[8], pj[8];
    float acc[8][8];   // [point i][feature j]
    #pragma unroll
    for (int j = 0; j < 8; j++) {
        int c = tx * 8 + j;
        fj[j] = __ldg(freq + c);
        pj[j] = __ldg(phase + c);
        float b = __ldg(bias + c);
        #pragma unroll
        for (int i = 0; i < 8; i++) acc[i][j] = b;
    }
    const float* xb = Xt + ty * 8;
    const float* wb = Wt + tx * 8;
    #pragma unroll 4
    for (int k = 0; k < K; k++) {
        float4 xa = *(const float4*)(xb + k * XS);
        float4 xc = *(const float4*)(xb + k * XS + 4);
        float4 wa = *(const float4*)(wb + k * XS);
        float4 wc = *(const float4*)(wb + k * XS + 4);
        float xf[8] = {xa.x, xa.y, xa.z, xa.w, xc.x, xc.y, xc.z, xc.w};
        float wf[8] = {wa.x, wa.y, wa.z, wa.w, wc.x, wc.y, wc.z, wc.w};
        #pragma unroll
        for (int j = 0; j < 8; j++)
            #pragma unroll
            for (int i = 0; i < 8; i++)
                acc[i][j] = fmaf(xf[i], wf[j], acc[i][j]);
    }
    __syncthreads();   // all reads of Xt/Wt done before overwrite
    #pragma unroll
    for (int j = 0; j < 8; j++) {
        float4 v0, v1;
        v0.x = fast_sin(fmaf(fj[j], acc[0][j], pj[j]));
        v0.y = fast_sin(fmaf(fj[j], acc[1][j], pj[j]));
        v0.z = fast_sin(fmaf(fj[j], acc[2][j], pj[j]));
        v0.w = fast_sin(fmaf(fj[j], acc[3][j], pj[j]));
        v1.x = fast_sin(fmaf(fj[j], acc[4][j], pj[j]));
        v1.y = fast_sin(fmaf(fj[j], acc[5][j], pj[j]));
        v1.z = fast_sin(fmaf(fj[j], acc[6][j], pj[j]));
        v1.w = fast_sin(fmaf(fj[j], acc[7][j], pj[j]));
        float* dst = Xt + (tx * 8 + j) * XS + ty * 8;
        *(float4*)dst = v0;
        *(float4*)(dst + 4) = v1;
    }
    __syncthreads();
}

// ---------------------------------------------------------------------------
// Fused main kernel: grid sample + 8 FiLM layers + sigma + color + clin
// CTA = 128 points, 256 threads, 1 CTA/SM
// ---------------------------------------------------------------------------
__global__ void __launch_bounds__(256, 1)
pigan_main(const float* __restrict__ input, const float* __restrict__ rdirs,
           const float* __restrict__ grid,
           const float* __restrict__ net_w0, const float* __restrict__ net_b0,
           const float* __restrict__ net_ws, const float* __restrict__ net_bs,
           const float* __restrict__ final_w, const float* __restrict__ final_b,
           const float* __restrict__ color_w, const float* __restrict__ color_b,
           const float* __restrict__ clin_w, const float* __restrict__ clin_b,
           float* __restrict__ out)
{
    extern __shared__ float sm[];
    float* Xt  = sm;                  // [131][XS]  features x points
    float* Wt  = sm + 131 * XS;       // [131][XS]  k x out-features
    float* aux = sm + 2 * 131 * XS;   // final_w[128] + clin_w[384]

    const int tid = threadIdx.x;
    const int tx = tid & 15;
    const int ty = tid >> 4;
    const int g0 = blockIdx.x * 128;      // global point base
    const int batch = g0 >> 16;           // N = 65536
    const float* fqb = g_freqs[batch];
    const float* phb = g_phases[batch];

    // ---- load coords (scaled) into rows 32..34 and ray dirs into 128..130
    for (int idx = tid; idx < 384; idx += 256) {
        int p = idx / 3, d = idx - p * 3;
        Xt[(32 + d) * XS + p]  = input[g0 * 3 + idx] * 8.3333333333333339f;
        Xt[(128 + d) * XS + p] = rdirs[g0 * 3 + idx];
    }
    __syncthreads();

    // ---- trilinear grid sample: 2 threads/point, 16 channels each
    {
        const int p = tid & 127;
        const int hf = tid >> 7;
        float fx = (Xt[32 * XS + p] + 1.f) * 0.5f * (GD - 1);
        float fy = (Xt[33 * XS + p] + 1.f) * 0.5f * (GD - 1);
        float fz = (Xt[34 * XS + p] + 1.f) * 0.5f * (GD - 1);
        int x0 = min(GD - 2, max(0, (int)floorf(fx)));
        int y0 = min(GD - 2, max(0, (int)floorf(fy)));
        int z0 = min(GD - 2, max(0, (int)floorf(fz)));
        float wx1 = fx - (float)x0, wx0 = 1.f - wx1;
        float wy1 = fy - (float)y0, wy0 = 1.f - wy1;
        float wz1 = fz - (float)z0, wz0 = 1.f - wz1;
        float w00 = wz0 * wy0, w01 = wz0 * wy1, w10 = wz1 * wy0, w11 = wz1 * wy1;
        int b00 = (z0 * GD + y0) * GD + x0;
        int b01 = b00 + GD;
        int b10 = b00 + GD * GD;
        int b11 = b10 + GD;
        const float* gp = grid + hf * 16 * GD * GD * GD;
        #pragma unroll 4
        for (int c = 0; c < 16; c++) {
            const float* g = gp + c * (GD * GD * GD);
            float a;
            a  = w00 * (wx0 * __ldg(g + b00) + wx1 * __ldg(g + b00 + 1));
            a += w01 * (wx0 * __ldg(g + b01) + wx1 * __ldg(g + b01 + 1));
            a += w10 * (wx0 * __ldg(g + b10) + wx1 * __ldg(g + b10 + 1));
            a += w11 * (wx0 * __ldg(g + b11) + wx1 * __ldg(g + b11 + 1));
            Xt[(hf * 16 + c) * XS + p] = a;
        }
    }
    __syncthreads();

    // ---- layer 0: K = 35 (32 feat + 3 coords)
    load_w<35>(Wt, net_w0, tid);
    do_film<35>(Xt, Wt, fqb, phb, net_b0, tx, ty);

    // ---- layers 1..7: K = 128
    for (int l = 0; l < NLAYERS - 1; l++) {
        load_w<128>(Wt, net_ws + l * HID * HID, tid);
        do_film<128>(Xt, Wt, fqb + (l + 1) * HID, phb + (l + 1) * HID,
                     net_bs + l * HID, tx, ty);
    }

    // ---- sigma = final_w . x + final_b
    if (tid < 128) aux[tid] = __ldg(final_w + tid);
    for (int idx = tid; idx < 384; idx += 256) aux[128 + idx] = __ldg(clin_w + idx);
    __syncthreads();
    if (tid < 128) {
        float acc = __ldg(final_b);
        #pragma unroll 4
        for (int k = 0; k < 128; k++) acc = fmaf(Xt[k * XS + tid], aux[k], acc);
        out[(size_t)(g0 + tid) * 4 + 3] = acc;
    }
    __syncthreads();

    // ---- color FiLM: K = 131 (x rows 0..127, rd rows 128..130)
    load_w_color(Wt, color_w, tid);
    do_film<131>(Xt, Wt, fqb + 8 * HID, phb + 8 * HID, color_b, tx, ty);

    // ---- clin (3x128) + sigmoid
    if (tid < 128) {
        const int p = tid;
        float a0 = __ldg(clin_b + 0);
        float a1 = __ldg(clin_b + 1);
        float a2 = __ldg(clin_b + 2);
        #pragma unroll 4
        for (int k = 0; k < 128; k++) {
            float xv = Xt[k * XS + p];
            a0 = fmaf(xv, aux[128 + k], a0);
            a1 = fmaf(xv, aux[256 + k], a1);
            a2 = fmaf(xv, aux[384 + k], a2);
        }
        size_t o = (size_t)(g0 + p) * 4;
        out[o + 0] = 1.f / (1.f + __expf(-a0));
        out[o + 1] = 1.f / (1.f + __expf(-a1));
        out[o + 2] = 1.f / (1.f + __expf(-a2));
    }
}

// ---------------------------------------------------------------------------
extern "C" void kernel_launch(void* const* d_in, const int* in_sizes, int n_in,
                              void* d_out, int out_size)
{
    const float* input = (const float*)d_in[0];
    const float* z     = (const float*)d_in[1];
    const float* rdirs = (const float*)d_in[2];
    const float* grid  = (const float*)d_in[3];
    const float* mw0 = (const float*)d_in[4];  const float* mb0 = (const float*)d_in[5];
    const float* mw1 = (const float*)d_in[6];  const float* mb1 = (const float*)d_in[7];
    const float* mw2 = (const float*)d_in[8];  const float* mb2 = (const float*)d_in[9];
    const float* mw3 = (const float*)d_in[10]; const float* mb3 = (const float*)d_in[11];
    const float* nw0 = (const float*)d_in[12]; const float* nb0 = (const float*)d_in[13];
    const float* nws = (const float*)d_in[14]; const float* nbs = (const float*)d_in[15];
    const float* fw  = (const float*)d_in[16]; const float* fb  = (const float*)d_in[17];
    const float* cw  = (const float*)d_in[18]; const float* cb  = (const float*)d_in[19];
    const float* lw  = (const float*)d_in[20]; const float* lb  = (const float*)d_in[21];
    float* out = (float*)d_out;

    cudaFuncSetAttribute(pigan_main,
                         cudaFuncAttributeMaxDynamicSharedMemorySize, SMEM_BYTES);

    map_kernel<<<BATCH, MAPH>>>(z, mw0, mb0, mw1, mb1, mw2, mb2, mw3, mb3);
    pigan_main<<<(BATCH * NPTS) / 128, 256, SMEM_BYTES>>>(
        input, rdirs, grid, nw0, nb0, nws, nbs, fw, fb, cw, cb, lw, lb, out);
}

// round 7
// speedup vs baseline: 1.5513x; 1.5513x over previous
#include <cuda_runtime.h>
#include <cuda_fp16.h>
#include <stdint.h>
#include <math.h>

#define HID 128
#define ZDIM 100
#define GD 96
#define BATCH 8
#define NPTS 65536
#define NLAYERS 8
#define MAPH 256
#define FDIM ((NLAYERS + 1) * HID)   // 1152

#define WSTRIDE 136                   // fp16 elements per W/X row (128 + 8 pad)
#define LAYER_ELS (128 * WSTRIDE)     // 17408 halves = 34816 bytes
#define WTOT (9 * LAYER_ELS)          // 156672

__device__ float g_freqs[BATCH][FDIM];
__device__ float g_phases[BATCH][FDIM];
__device__ float g_pc[BATCH][FDIM];
__device__ __align__(1024) __half g_Whi[WTOT];
__device__ __align__(1024) __half g_Wlo[WTOT];

// ---- SMEM layout ----
#define SM_XHI 0                      // 128*136*2 = 34816
#define SM_XLO 34816
#define SM_WB0 69632                  // hi @ +0, lo @ +34816
#define SM_WB1 139264
#define AX_WMBAR0 208896
#define AX_WMBAR1 208904
#define AX_COORD  208912              // 3*128 f32
#define AX_RD     210448              // 3*128 f32
#define AX_SSUM   211984              // 4*128 f32
#define AX_CSUM   214032              // 4*3*128 f32
#define AX_FREQ   220176              // 2 stages * 128 f32
#define AX_PC     221200              // 2 stages * 128 f32
#define SMEM_TOTAL 222224

// ---------------------------------------------------------------------------
static __device__ __forceinline__ uint32_t smem_u32(const void* p) {
    uint32_t a;
    asm("{ .reg .u64 t; cvta.to.shared.u64 t, %1; cvt.u32.u64 %0, t; }" : "=r"(a) : "l"(p));
    return a;
}

#define MBARRIER_INIT(a, c) \
    asm volatile("mbarrier.init.shared.b64 [%0], %1;" :: "r"((uint32_t)(a)), "r"((uint32_t)(c)) : "memory")
#define MBARRIER_EXPECT_TX(a, t) \
    asm volatile("mbarrier.arrive.expect_tx.shared.b64 _, [%0], %1;" :: "r"((uint32_t)(a)), "r"((uint32_t)(t)) : "memory")

#define MBARRIER_WAIT_PARITY(mbar_addr, phase_parity) do { \
    uint32_t _mbar = (uint32_t)(mbar_addr); \
    uint32_t _parity = (uint32_t)(phase_parity); \
    uint32_t _done; \
    asm volatile("{\n\t.reg .pred p;\n\t" \
        "mbarrier.try_wait.parity.acquire.cta.shared::cta.b64 p, [%1], %2;\n\t" \
        "selp.b32 %0, 1, 0, p;\n\t}" : "=r"(_done) : "r"(_mbar), "r"(_parity) : "memory"); \
    if (!_done) { \
        asm volatile("{\n\t.reg .pred P1;\n\t" \
            "WAIT_LOOP_%=:\n\t" \
            "mbarrier.try_wait.parity.acquire.cta.shared::cta.b64 P1, [%0], %1, 0x989680;\n\t" \
            "@P1 bra.uni WAIT_DONE_%=;\n\t" \
            "bra.uni WAIT_LOOP_%=;\n\t" \
            "WAIT_DONE_%=:\n\t}" :: "r"(_mbar), "r"(_parity) : "memory"); \
    } \
} while (0)

static __device__ __forceinline__ void bulk_g2s(uint32_t dst, const void* src, uint32_t bytes, uint32_t mbar) {
    asm volatile("cp.async.bulk.shared::cta.global.mbarrier::complete_tx::bytes [%0], [%1], %2, [%3];"
        :: "r"(dst), "l"(src), "r"(bytes), "r"(mbar) : "memory");
}

// m16n8k16 row.col f32.f16.f16.f32
static __device__ __forceinline__ void mma16816(float* c, const uint32_t* a, const uint32_t* b) {
    asm volatile(
        "mma.sync.aligned.m16n8k16.row.col.f32.f16.f16.f32 "
        "{%0,%1,%2,%3}, {%4,%5,%6,%7}, {%8,%9}, {%0,%1,%2,%3};"
        : "+f"(c[0]), "+f"(c[1]), "+f"(c[2]), "+f"(c[3])
        : "r"(a[0]), "r"(a[1]), "r"(a[2]), "r"(a[3]), "r"(b[0]), "r"(b[1]));
}

static __device__ __forceinline__ uint32_t lds32(const __half* base, int row, int col) {
    return *reinterpret_cast<const uint32_t*>(base + row * WSTRIDE + col);
}

__device__ __forceinline__ float fast_sin(float x) {
    float n = rintf(x * 0.15915494309189535f);
    float r = fmaf(n, -6.28125f, x);
    r = fmaf(n, -1.9353071795864769e-3f, r);
    return __sinf(r);
}

__device__ __forceinline__ void split16(float v, __half& hi, __half& lo) {
    hi = __float2half_rn(v);
    lo = __float2half_rn(v - __half2float(hi));
}

// ---------------------------------------------------------------------------
// Mapping network (72 CTAs = 8 batches x 9 slices)
// ---------------------------------------------------------------------------
__global__ void map_kernel(const float* __restrict__ z,
                           const float* __restrict__ w0, const float* __restrict__ b0,
                           const float* __restrict__ w1, const float* __restrict__ b1,
                           const float* __restrict__ w2, const float* __restrict__ b2,
                           const float* __restrict__ w3, const float* __restrict__ b3)
{
    __shared__ float zs[ZDIM];
    __shared__ float ha[MAPH];
    __shared__ float hb[MAPH];
    const int b = blockIdx.x / 9;
    const int slice = blockIdx.x % 9;
    const int tid = threadIdx.x;

    if (tid < ZDIM) zs[tid] = z[b * ZDIM + tid];
    __syncthreads();
    {
        float acc = b0[tid];
        const float* wr = w0 + tid * ZDIM;
        #pragma unroll 4
        for (int k = 0; k < ZDIM; k++) acc = fmaf(wr[k], zs[k], acc);
        ha[tid] = acc > 0.f ? acc : 0.2f * acc;
    }
    __syncthreads();
    {
        float acc = b1[tid];
        const float* wr = w1 + tid * MAPH;
        #pragma unroll 4
        for (int k = 0; k < MAPH; k++) acc = fmaf(wr[k], ha[k], acc);
        hb[tid] = acc > 0.f ? acc : 0.2f * acc;
    }
    __syncthreads();
    {
        float acc = b2[tid];
        const float* wr = w2 + tid * MAPH;
        #pragma unroll 4
        for (int k = 0; k < MAPH; k++) acc = fmaf(wr[k], hb[k], acc);
        ha[tid] = acc > 0.f ? acc : 0.2f * acc;
    }
    __syncthreads();
    {
        int o = slice * 256 + tid;
        float acc = b3[o];
        const float* wr = w3 + o * MAPH;
        #pragma unroll 4
        for (int k = 0; k < MAPH; k++) acc = fmaf(wr[k], ha[k], acc);
        if (o < FDIM) g_freqs[b][o] = fmaf(acc, 15.f, 30.f);
        else          g_phases[b][o - FDIM] = acc;
    }
}

__global__ void fold_kernel(const float* __restrict__ nb0, const float* __restrict__ nbs,
                            const float* __restrict__ cb)
{
    const int b = blockIdx.x / 9;
    const int c = (blockIdx.x % 9) * 128 + threadIdx.x;
    float bias = (c < 128) ? nb0[c] : (c < 1024 ? nbs[c - 128] : cb[c - 1024]);
    g_pc[b][c] = fmaf(g_freqs[b][c], bias, g_phases[b][c]);
}

// split all weights into fp16 hi/lo, padded [9][128][136]
__global__ void wsplit_kernel(const float* __restrict__ nw0, const float* __restrict__ nws,
                              const float* __restrict__ cw)
{
    int e = blockIdx.x * 256 + threadIdx.x;
    if (e >= WTOT) return;
    int l = e / LAYER_ELS;
    int rem = e - l * LAYER_ELS;
    int n = rem / WSTRIDE;
    int k = rem - n * WSTRIDE;
    float v = 0.f;
    if (l == 0)      { if (k < 35)  v = nw0[n * 35 + k]; }
    else if (l <= 7) { if (k < 128) v = nws[(l - 1) * 16384 + n * 128 + k]; }
    else             { if (k < 128) v = cw[n * 131 + 3 + k]; }
    __half hi, lo;
    split16(v, hi, lo);
    g_Whi[e] = hi;
    g_Wlo[e] = lo;
}

// ---------------------------------------------------------------------------
// Main fused kernel: grid sample + 9 FiLM GEMMs (HMMA fp16-split) + outputs
// ---------------------------------------------------------------------------
__global__ void __launch_bounds__(512, 1)
pigan_main(const float* __restrict__ input, const float* __restrict__ rdirs,
           const float* __restrict__ gridv,
           const float* __restrict__ cw,
           const float* __restrict__ fw, const float* __restrict__ fb,
           const float* __restrict__ lw, const float* __restrict__ lb,
           float* __restrict__ out)
{
    extern __shared__ __align__(1024) char sm[];
    const uint32_t smb = smem_u32(sm);
    __half* Xhi = (__half*)(sm + SM_XHI);
    __half* Xlo = (__half*)(sm + SM_XLO);
    float* coords_s = (float*)(sm + AX_COORD);
    float* rd_s     = (float*)(sm + AX_RD);
    float* ssum     = (float*)(sm + AX_SSUM);
    float* csum     = (float*)(sm + AX_CSUM);
    float* fq_s     = (float*)(sm + AX_FREQ);   // [2][128]
    float* pc_s     = (float*)(sm + AX_PC);     // [2][128]

    const int tid = threadIdx.x;
    const int wid = tid >> 5;
    const int lane = tid & 31;
    const int g = lane >> 2, tig = lane & 3;
    const int m0 = (wid & 3) * 32;
    const int n0 = (wid >> 2) * 32;
    const int g0 = blockIdx.x * 128;
    const int batch = blockIdx.x >> 9;

    const uint32_t wmbar[2] = { smb + AX_WMBAR0, smb + AX_WMBAR1 };

    if (tid == 0) {
        MBARRIER_INIT(wmbar[0], 1);
        MBARRIER_INIT(wmbar[1], 1);
    }
    __syncthreads();

    // kick off weight loads for layers 0, 1
    if (tid == 0) {
        MBARRIER_EXPECT_TX(wmbar[0], 69632);
        bulk_g2s(smb + SM_WB0,         (const char*)g_Whi, 34816, wmbar[0]);
        bulk_g2s(smb + SM_WB0 + 34816, (const char*)g_Wlo, 34816, wmbar[0]);
        MBARRIER_EXPECT_TX(wmbar[1], 69632);
        bulk_g2s(smb + SM_WB1,         (const char*)(g_Whi + LAYER_ELS), 34816, wmbar[1]);
        bulk_g2s(smb + SM_WB1 + 34816, (const char*)(g_Wlo + LAYER_ELS), 34816, wmbar[1]);
    }

    // coords + ray dirs
    for (int idx = tid; idx < 384; idx += 512) {
        int pp = idx / 3, d = idx - pp * 3;
        coords_s[d * 128 + pp] = input[g0 * 3 + idx] * 8.3333333333333339f;
        rd_s[d * 128 + pp]     = rdirs[g0 * 3 + idx];
    }
    __syncthreads();

    // grid sample: 4 threads/point, 8 channels each; coords->cols 32..34; zero 35..63
    {
        const int p = tid & 127;
        const int hf = tid >> 7;    // 0..3
        float fx = (coords_s[0 * 128 + p] + 1.f) * 0.5f * (GD - 1);
        float fy = (coords_s[1 * 128 + p] + 1.f) * 0.5f * (GD - 1);
        float fz = (coords_s[2 * 128 + p] + 1.f) * 0.5f * (GD - 1);
        int x0 = min(GD - 2, max(0, (int)floorf(fx)));
        int y0 = min(GD - 2, max(0, (int)floorf(fy)));
        int z0 = min(GD - 2, max(0, (int)floorf(fz)));
        float wx1 = fx - (float)x0, wx0 = 1.f - wx1;
        float wy1 = fy - (float)y0, wy0 = 1.f - wy1;
        float wz1 = fz - (float)z0, wz0 = 1.f - wz1;
        float w00 = wz0 * wy0, w01 = wz0 * wy1, w10 = wz1 * wy0, w11 = wz1 * wy1;
        int b00 = (z0 * GD + y0) * GD + x0;
        int b01 = b00 + GD;
        int b10 = b00 + GD * GD;
        int b11 = b10 + GD;
        const float* gp = gridv + hf * 8 * GD * GD * GD;
        #pragma unroll 4
        for (int c = 0; c < 8; c++) {
            const float* gg = gp + c * (GD * GD * GD);
            float a;
            a  = w00 * (wx0 * __ldg(gg + b00) + wx1 * __ldg(gg + b00 + 1));
            a += w01 * (wx0 * __ldg(gg + b01) + wx1 * __ldg(gg + b01 + 1));
            a += w10 * (wx0 * __ldg(gg + b10) + wx1 * __ldg(gg + b10 + 1));
            a += w11 * (wx0 * __ldg(gg + b11) + wx1 * __ldg(gg + b11 + 1));
            __half h, l; split16(a, h, l);
            int col = hf * 8 + c;
            Xhi[p * WSTRIDE + col] = h;
            Xlo[p * WSTRIDE + col] = l;
        }
        if (hf == 0) {
            #pragma unroll
            for (int d = 0; d < 3; d++) {
                __half h, l; split16(coords_s[d * 128 + p], h, l);
                Xhi[p * WSTRIDE + 32 + d] = h;
                Xlo[p * WSTRIDE + 32 + d] = l;
            }
        } else if (hf == 3) {
            for (int c = 35; c < 64; c++) {
                Xhi[p * WSTRIDE + c] = __float2half_rn(0.f);
                Xlo[p * WSTRIDE + c] = __float2half_rn(0.f);
            }
        }
    }
    __syncthreads();

    // -------- 9 rounds: layers 0..7 + color --------
    for (int r = 0; r <= 8; r++) {
        const int stage = r & 1;
        const __half* Whi = (const __half*)(sm + (stage ? SM_WB1 : SM_WB0));
        const __half* Wlo = Whi + LAYER_ELS;

        // stage freq / pc for this layer (double-buffered by stage)
        if (tid < 128) {
            fq_s[stage * 128 + tid] = g_freqs[batch][r * HID + tid];
            pc_s[stage * 128 + tid] = g_pc[batch][r * HID + tid];
        }

        MBARRIER_WAIT_PARITY(wmbar[stage], (r >> 1) & 1);

        // ---- MMA: warp tile 32m x 32n, fp16 two-split (3 mma per product) ----
        float c[2][4][4];
        #pragma unroll
        for (int mf = 0; mf < 2; mf++)
            #pragma unroll
            for (int nt = 0; nt < 4; nt++)
                #pragma unroll
                for (int q = 0; q < 4; q++) c[mf][nt][q] = 0.f;

        const int nks = (r == 0) ? 4 : 8;
        for (int ks = 0; ks < nks; ks++) {
            const int k0 = ks * 16;
            uint32_t ahi[2][4], alo[2][4], bhi[4][2], blo[4][2];
            #pragma unroll
            for (int mf = 0; mf < 2; mf++) {
                int row = m0 + mf * 16 + g;
                ahi[mf][0] = lds32(Xhi, row,     k0 + tig * 2);
                ahi[mf][1] = lds32(Xhi, row + 8, k0 + tig * 2);
                ahi[mf][2] = lds32(Xhi, row,     k0 + 8 + tig * 2);
                ahi[mf][3] = lds32(Xhi, row + 8, k0 + 8 + tig * 2);
                alo[mf][0] = lds32(Xlo, row,     k0 + tig * 2);
                alo[mf][1] = lds32(Xlo, row + 8, k0 + tig * 2);
                alo[mf][2] = lds32(Xlo, row,     k0 + 8 + tig * 2);
                alo[mf][3] = lds32(Xlo, row + 8, k0 + 8 + tig * 2);
            }
            #pragma unroll
            for (int nt = 0; nt < 4; nt++) {
                int nrow = n0 + nt * 8 + g;
                bhi[nt][0] = lds32(Whi, nrow, k0 + tig * 2);
                bhi[nt][1] = lds32(Whi, nrow, k0 + 8 + tig * 2);
                blo[nt][0] = lds32(Wlo, nrow, k0 + tig * 2);
                blo[nt][1] = lds32(Wlo, nrow, k0 + 8 + tig * 2);
            }
            #pragma unroll
            for (int mf = 0; mf < 2; mf++)
                #pragma unroll
                for (int nt = 0; nt < 4; nt++) {
                    mma16816(c[mf][nt], ahi[mf], bhi[nt]);
                    mma16816(c[mf][nt], ahi[mf], blo[nt]);
                    mma16816(c[mf][nt], alo[mf], bhi[nt]);
                }
        }
        __syncthreads();   // all warps done reading X & W stage

        // prefetch W for layer r+2 into freed stage
        if (tid == 0 && r + 2 <= 8) {
            MBARRIER_EXPECT_TX(wmbar[stage], 69632);
            uint32_t wboff = stage ? SM_WB1 : SM_WB0;
            bulk_g2s(smb + wboff,         (const char*)(g_Whi + (r + 2) * LAYER_ELS), 34816, wmbar[stage]);
            bulk_g2s(smb + wboff + 34816, (const char*)(g_Wlo + (r + 2) * LAYER_ELS), 34816, wmbar[stage]);
        }

        // ---- epilogue: sin, re-split, writeback / reductions ----
        const float* fq = fq_s + stage * 128;
        const float* pc = pc_s + stage * 128;
        float sp[4] = {0.f, 0.f, 0.f, 0.f};
        float cp0[4] = {0.f, 0.f, 0.f, 0.f};
        float cp1[4] = {0.f, 0.f, 0.f, 0.f};
        float cp2[4] = {0.f, 0.f, 0.f, 0.f};

        #pragma unroll
        for (int mf = 0; mf < 2; mf++)
            #pragma unroll
            for (int rg = 0; rg < 2; rg++) {
                int row = m0 + mf * 16 + rg * 8 + g;
                float rv0 = 0.f, rv1 = 0.f, rv2 = 0.f;
                if (r == 8) { rv0 = rd_s[row]; rv1 = rd_s[128 + row]; rv2 = rd_s[256 + row]; }
                #pragma unroll
                for (int nt = 0; nt < 4; nt++) {
                    int col = n0 + nt * 8 + tig * 2;
                    float v0 = c[mf][nt][rg * 2 + 0];
                    float v1 = c[mf][nt][rg * 2 + 1];
                    if (r == 8) {
                        const float* w0p = cw + (size_t)col * 131;
                        const float* w1p = w0p + 131;
                        v0 = fmaf(rv0, __ldg(w0p), fmaf(rv1, __ldg(w0p + 1), fmaf(rv2, __ldg(w0p + 2), v0)));
                        v1 = fmaf(rv0, __ldg(w1p), fmaf(rv1, __ldg(w1p + 1), fmaf(rv2, __ldg(w1p + 2), v1)));
                    }
                    float s0 = fast_sin(fmaf(fq[col],     v0, pc[col]));
                    float s1 = fast_sin(fmaf(fq[col + 1], v1, pc[col + 1]));
                    if (r < 8) {
                        __half h0, l0, h1, l1;
                        split16(s0, h0, l0);
                        split16(s1, h1, l1);
                        *(__half2*)(Xhi + row * WSTRIDE + col) = __halves2half2(h0, h1);
                        *(__half2*)(Xlo + row * WSTRIDE + col) = __halves2half2(l0, l1);
                    }
                    if (r == 7) {
                        sp[mf * 2 + rg] = fmaf(s0, __ldg(fw + col), fmaf(s1, __ldg(fw + col + 1), sp[mf * 2 + rg]));
                    }
                    if (r == 8) {
                        int i = mf * 2 + rg;
                        cp0[i] = fmaf(s0, __ldg(lw + col),       fmaf(s1, __ldg(lw + col + 1),       cp0[i]));
                        cp1[i] = fmaf(s0, __ldg(lw + 128 + col), fmaf(s1, __ldg(lw + 128 + col + 1), cp1[i]));
                        cp2[i] = fmaf(s0, __ldg(lw + 256 + col), fmaf(s1, __ldg(lw + 256 + col + 1), cp2[i]));
                    }
                }
            }

        if (r == 7) {
            #pragma unroll
            for (int i = 0; i < 4; i++) {
                sp[i] += __shfl_xor_sync(0xFFFFFFFF, sp[i], 1);
                sp[i] += __shfl_xor_sync(0xFFFFFFFF, sp[i], 2);
            }
            if (tig == 0) {
                #pragma unroll
                for (int i = 0; i < 4; i++) {
                    int row = m0 + (i >> 1) * 16 + (i & 1) * 8 + g;
                    ssum[(wid >> 2) * 128 + row] = sp[i];
                }
            }
        }
        if (r == 8) {
            #pragma unroll
            for (int i = 0; i < 4; i++) {
                cp0[i] += __shfl_xor_sync(0xFFFFFFFF, cp0[i], 1);
                cp0[i] += __shfl_xor_sync(0xFFFFFFFF, cp0[i], 2);
                cp1[i] += __shfl_xor_sync(0xFFFFFFFF, cp1[i], 1);
                cp1[i] += __shfl_xor_sync(0xFFFFFFFF, cp1[i], 2);
                cp2[i] += __shfl_xor_sync(0xFFFFFFFF, cp2[i], 1);
                cp2[i] += __shfl_xor_sync(0xFFFFFFFF, cp2[i], 2);
            }
            if (tig == 0) {
                #pragma unroll
                for (int i = 0; i < 4; i++) {
                    int row = m0 + (i >> 1) * 16 + (i & 1) * 8 + g;
                    csum[((wid >> 2) * 3 + 0) * 128 + row] = cp0[i];
                    csum[((wid >> 2) * 3 + 1) * 128 + row] = cp1[i];
                    csum[((wid >> 2) * 3 + 2) * 128 + row] = cp2[i];
                }
            }
        }
        __syncthreads();

        if (r == 7 && tid < 128) {
            float s = ssum[tid] + ssum[128 + tid] + ssum[256 + tid] + ssum[384 + tid] + __ldg(fb);
            out[(size_t)(g0 + tid) * 4 + 3] = s;
        }
    }

    // rgb output
    if (tid < 128) {
        #pragma unroll
        for (int i = 0; i < 3; i++) {
            float v = csum[(0 * 3 + i) * 128 + tid] + csum[(1 * 3 + i) * 128 + tid]
                    + csum[(2 * 3 + i) * 128 + tid] + csum[(3 * 3 + i) * 128 + tid] + __ldg(lb + i);
            out[(size_t)(g0 + tid) * 4 + i] = 1.f / (1.f + __expf(-v));
        }
    }
}

// ---------------------------------------------------------------------------
extern "C" void kernel_launch(void* const* d_in, const int* in_sizes, int n_in,
                              void* d_out, int out_size)
{
    const float* input = (const float*)d_in[0];
    const float* z     = (const float*)d_in[1];
    const float* rdirs = (const float*)d_in[2];
    const float* grid  = (const float*)d_in[3];
    const float* mw0 = (const float*)d_in[4];  const float* mb0 = (const float*)d_in[5];
    const float* mw1 = (const float*)d_in[6];  const float* mb1 = (const float*)d_in[7];
    const float* mw2 = (const float*)d_in[8];  const float* mb2 = (const float*)d_in[9];
    const float* mw3 = (const float*)d_in[10]; const float* mb3 = (const float*)d_in[11];
    const float* nw0 = (const float*)d_in[12]; const float* nb0 = (const float*)d_in[13];
    const float* nws = (const float*)d_in[14]; const float* nbs = (const float*)d_in[15];
    const float* fw  = (const float*)d_in[16]; const float* fb  = (const float*)d_in[17];
    const float* cw  = (const float*)d_in[18]; const float* cb  = (const float*)d_in[19];
    const float* lw  = (const float*)d_in[20]; const float* lb  = (const float*)d_in[21];
    float* out = (float*)d_out;

    cudaFuncSetAttribute(pigan_main,
                         cudaFuncAttributeMaxDynamicSharedMemorySize, SMEM_TOTAL);

    map_kernel<<<72, 256>>>(z, mw0, mb0, mw1, mb1, mw2, mb2, mw3, mb3);
    fold_kernel<<<72, 128>>>(nb0, nbs, cb);
    wsplit_kernel<<<(WTOT + 255) / 256, 256>>>(nw0, nws, cw);
    pigan_main<<<(BATCH * NPTS) / 128, 512, SMEM_TOTAL>>>(
        input, rdirs, grid, cw, fw, fb, lw, lb, out);
}